// round 13
// baseline (speedup 1.0000x reference)
#include <cuda_runtime.h>
#include <cuda_fp16.h>
#include <math.h>
#include <stdint.h>

// Problem constants
#define BB 4
#define TT 2048
#define CC 768
#define HH 12
#define DD 64
#define NROWS (BB*TT)          // 8192
#define QKVC (3*CC)            // 2304
#define FFC (4*CC)             // 3072

#define QSCALE (0.125f * 1.4426950408889634f)   // 1/sqrt(D) * log2(e)

// ================= scratch (allocation-free: __device__ globals) =================
__device__ __half g_h1[NROWS*CC];
__device__ __half g_y [NROWS*CC];
__device__ float  g_x1[NROWS*CC];
__device__ __half g_h2[NROWS*CC];
__device__ __half g_fc[NROWS*FFC];
__device__ __half g_wq[QKVC*CC];   // [N][K] K-major, single fp16
__device__ __half g_wa[CC*CC];
__device__ __half g_wf[FFC*CC];
__device__ __half g_wm[CC*FFC];
// per-head q/k/v: [b*H+h][T][64], single fp16 (Q pre-scaled)
__device__ __half g_qs[NROWS*CC];
__device__ __half g_ks[NROWS*CC];
__device__ __half g_vs[NROWS*CC];

__device__ __forceinline__ uint32_t packh2(__half a, __half b) {
    return (uint32_t)__half_as_ushort(a) | ((uint32_t)__half_as_ushort(b) << 16);
}
__device__ __forceinline__ uint32_t smem_u32(const void* p) {
    uint32_t a;
    asm("{ .reg .u64 t; cvta.to.shared.u64 t, %1; cvt.u32.u64 %0, t; }" : "=r"(a) : "l"(p));
    return a;
}
__device__ __forceinline__ void cp16(uint32_t saddr, const void* g) {
    asm volatile("cp.async.cg.shared.global [%0], [%1], 16;" :: "r"(saddr), "l"(g));
}
#define CP_COMMIT() asm volatile("cp.async.commit_group;" ::: "memory")
#define CP_WAIT1()  asm volatile("cp.async.wait_group 1;" ::: "memory")
#define CP_WAIT0()  asm volatile("cp.async.wait_group 0;" ::: "memory")

__device__ __forceinline__ void ldm_x4(uint32_t* r, uint32_t addr) {
    asm volatile("ldmatrix.sync.aligned.m8n8.x4.shared.b16 {%0,%1,%2,%3}, [%4];"
        : "=r"(r[0]), "=r"(r[1]), "=r"(r[2]), "=r"(r[3]) : "r"(addr));
}
__device__ __forceinline__ void ldm_x4_trans(uint32_t* r, uint32_t addr) {
    asm volatile("ldmatrix.sync.aligned.m8n8.x4.trans.shared.b16 {%0,%1,%2,%3}, [%4];"
        : "=r"(r[0]), "=r"(r[1]), "=r"(r[2]), "=r"(r[3]) : "r"(addr));
}
__device__ __forceinline__ void mma_f16(float* c, const uint32_t* a, const uint32_t* b) {
    asm volatile("mma.sync.aligned.m16n8k16.row.col.f32.f16.f16.f32 "
        "{%0,%1,%2,%3}, {%4,%5,%6,%7}, {%8,%9}, {%0,%1,%2,%3};"
        : "+f"(c[0]), "+f"(c[1]), "+f"(c[2]), "+f"(c[3])
        : "r"(a[0]), "r"(a[1]), "r"(a[2]), "r"(a[3]), "r"(b[0]), "r"(b[1]));
}
#define SMEM_SWIZZLE_128B(o) ((o) ^ (((o) >> 3) & 0x70))

__device__ __forceinline__ float gelu_tanh(float v) {
    const float c = 0.7978845608028654f;
    float u = c * (v + 0.044715f * v * v * v);
    return 0.5f * v * (1.0f + tanhf(u));
}

// ================= device helpers: weight transpose tile + LN row-block =================
__device__ __forceinline__ void tsplit_tile(const float* __restrict__ w,
                                            __half* __restrict__ th,
                                            int K, int N, int bx, int by,
                                            float (*tile)[33])
{
    const int tx = threadIdx.x & 31, ty = threadIdx.x >> 5;   // 32x8
    const int n0 = bx * 32, k0 = by * 32;
    #pragma unroll
    for (int r = 0; r < 4; ++r)
        tile[ty + 8*r][tx] = w[(size_t)(k0 + ty + 8*r) * N + n0 + tx];
    __syncthreads();
    #pragma unroll
    for (int r = 0; r < 4; ++r)
        th[(size_t)(n0 + ty + 8*r) * K + k0 + tx] = __float2half_rn(tile[tx][ty + 8*r]);
}

__device__ __forceinline__ void ln_rows(const float* __restrict__ x,
                                        const float* __restrict__ g,
                                        const float* __restrict__ bt,
                                        __half* __restrict__ oh, int rowblk)
{
    const int row  = rowblk * 8 + (threadIdx.x >> 5);
    const int lane = threadIdx.x & 31;
    const float* xr = x + (size_t)row * CC;

    float4 v[6];
    float sum = 0.f;
    #pragma unroll
    for (int i = 0; i < 6; ++i) {
        v[i] = *(const float4*)(xr + lane*4 + i*128);
        sum += (v[i].x + v[i].y) + (v[i].z + v[i].w);
    }
    #pragma unroll
    for (int off = 16; off > 0; off >>= 1) sum += __shfl_xor_sync(0xffffffffu, sum, off);
    const float mu = sum * (1.0f/768.0f);
    float var = 0.f;
    #pragma unroll
    for (int i = 0; i < 6; ++i) {
        float dx;
        dx = v[i].x - mu; var += dx*dx;  dx = v[i].y - mu; var += dx*dx;
        dx = v[i].z - mu; var += dx*dx;  dx = v[i].w - mu; var += dx*dx;
    }
    #pragma unroll
    for (int off = 16; off > 0; off >>= 1) var += __shfl_xor_sync(0xffffffffu, var, off);
    const float rstd = rsqrtf(var * (1.0f/768.0f) + 1e-5f);

    #pragma unroll
    for (int i = 0; i < 6; ++i) {
        const int col = lane*4 + i*128;
        const float4 gg = *(const float4*)(g  + col);
        const float4 bb = *(const float4*)(bt + col);
        const float r0 = (v[i].x - mu)*rstd*gg.x + bb.x;
        const float r1 = (v[i].y - mu)*rstd*gg.y + bb.y;
        const float r2 = (v[i].z - mu)*rstd*gg.z + bb.z;
        const float r3 = (v[i].w - mu)*rstd*gg.w + bb.w;
        const size_t o = (size_t)row * CC + col;
        *(uint2*)(oh + o) = make_uint2(
            packh2(__float2half_rn(r0), __float2half_rn(r1)),
            packh2(__float2half_rn(r2), __float2half_rn(r3)));
    }
}

// ================= fused prep: 4 weight transposes + LN1, one launch =================
__global__ __launch_bounds__(256) void prep_kernel(
    const float* __restrict__ w_attn, const float* __restrict__ w_aproj,
    const float* __restrict__ w_fc,   const float* __restrict__ w_mproj,
    __half* __restrict__ wq, __half* __restrict__ wa,
    __half* __restrict__ wf, __half* __restrict__ wm,
    const float* __restrict__ x, const float* __restrict__ ln1_g,
    const float* __restrict__ ln1_b, __half* __restrict__ h1)
{
    __shared__ float tile[32][33];
    int id = blockIdx.x;
    if (id < 1728) {
        tsplit_tile(w_attn, wq, CC, QKVC, id % 72, id / 72, tile);
    } else if (id < 2304) {
        id -= 1728;
        tsplit_tile(w_aproj, wa, CC, CC, id % 24, id / 24, tile);
    } else if (id < 4608) {
        id -= 2304;
        tsplit_tile(w_fc, wf, CC, FFC, id % 96, id / 96, tile);
    } else if (id < 6912) {
        id -= 4608;
        tsplit_tile(w_mproj, wm, FFC, CC, id % 24, id / 24, tile);
    } else {
        ln_rows(x, ln1_g, ln1_b, h1, id - 6912);
    }
}

// ================= LayerNorm -> single fp16 (LN2) =================
__global__ __launch_bounds__(256) void ln_h_kernel(const float* __restrict__ x,
                                                   const float* __restrict__ g,
                                                   const float* __restrict__ bt,
                                                   __half* __restrict__ oh)
{
    ln_rows(x, g, bt, oh, blockIdx.x);
}

// ========== single-term fp16 HMMA GEMM: R8 tiling + 3-stage single-sync pipeline ==========
// D[M,N] = A16[M,K] @ W16^T + bias, epilogues:
// EPI 1 = bias+gelu -> fp16; EPI 2 = bias+res -> fp32; EPI 3 = qkv per-head
#define TEN_BYTES 18432              // 128 rows * 72 elems * 2B
#define STAGE_BYTES (2*TEN_BYTES)    // A, B = 36864
#define GEMM_SMEM (3*STAGE_BYTES)    // 110592 -> 2 CTAs/SM (221KB)
#define ROWB 144

template<int EPI>
__global__ __launch_bounds__(256, 2) void hmma_gemm(
    const __half* __restrict__ Aa,
    const __half* __restrict__ Bw,
    const float* __restrict__ bias, const float* __restrict__ res,
    float* __restrict__ outF, __half* __restrict__ outH,
    __half* __restrict__ oks, __half* __restrict__ ovs,
    int M, int N, int K)
{
    extern __shared__ __align__(1024) char smem[];
    const uint32_t sb = smem_u32(smem);

    const int t    = threadIdx.x;
    const int lane = t & 31;
    const int wid  = t >> 5;
    const int warp_m = wid >> 2;
    const int warp_n = wid & 3;
    const int n0 = blockIdx.x * 128;
    const int m0 = blockIdx.y * 128;

    float acc[4][4][4];
    #pragma unroll
    for (int i = 0; i < 4; ++i)
        #pragma unroll
        for (int j = 0; j < 4; ++j)
            #pragma unroll
            for (int e = 0; e < 4; ++e) acc[i][j][e] = 0.f;

    const uint32_t aBase = sb + 0*TEN_BYTES + (uint32_t)(warp_m*64 + (lane & 15)) * ROWB + (lane >> 4) * 16;
    const uint32_t bRow   = (uint32_t)((lane & 7) + ((lane >> 4) << 3));
    const uint32_t bCol16 = (uint32_t)(((lane >> 3) & 1) * 16);
    const uint32_t bBase = sb + 1*TEN_BYTES + (uint32_t)(warp_n*32 + bRow) * ROWB + bCol16;

    const int nch = K >> 6;

    auto load_stage = [&](int buf, int k0) {
        const uint32_t dst = sb + (uint32_t)buf * STAGE_BYTES;
        #pragma unroll
        for (int i = 0; i < 4; ++i) {
            const int idx = i * 256 + t;
            const int row = idx >> 3;
            const int seg = idx & 7;
            const uint32_t so = (uint32_t)row * ROWB + seg * 16;
            cp16(dst + 0*TEN_BYTES + so, Aa + (size_t)(m0 + row) * K + k0 + seg * 8);
            cp16(dst + 1*TEN_BYTES + so, Bw + (size_t)(n0 + row) * K + k0 + seg * 8);
        }
    };

    load_stage(0, 0);
    CP_COMMIT();
    load_stage(1, 64);
    CP_COMMIT();

    int buf = 0;
    for (int ch = 0; ch < nch; ++ch) {
        if (ch + 1 < nch) { CP_WAIT1(); } else { CP_WAIT0(); }
        __syncthreads();
        if (ch + 2 < nch) {
            int nb = buf + 2; if (nb >= 3) nb -= 3;
            load_stage(nb, (ch + 2) << 6);
            CP_COMMIT();
        }

        const uint32_t st = (uint32_t)buf * STAGE_BYTES;
        #pragma unroll
        for (int ks = 0; ks < 4; ++ks) {
            const uint32_t kb = ks * 32;
            uint32_t af[4][4];
            #pragma unroll
            for (int fm = 0; fm < 4; ++fm)
                ldm_x4(af[fm], aBase + st + fm * (16 * ROWB) + kb);
            uint32_t bf[2][4];
            #pragma unroll
            for (int p = 0; p < 2; ++p)
                ldm_x4(bf[p], bBase + st + p * (16 * ROWB) + kb);
            #pragma unroll
            for (int fm = 0; fm < 4; ++fm)
                #pragma unroll
                for (int fn = 0; fn < 4; ++fn)
                    mma_f16(acc[fm][fn], af[fm], bf[fn >> 1] + (fn & 1) * 2);
        }
        ++buf; if (buf >= 3) buf -= 3;
    }

    #pragma unroll
    for (int fm = 0; fm < 4; ++fm) {
        const int row0 = m0 + warp_m*64 + fm*16 + (lane >> 2);
        #pragma unroll
        for (int fn = 0; fn < 4; ++fn) {
            const int col = n0 + warp_n*32 + fn*8 + (lane & 3)*2;
            const float b0 = bias[col], b1 = bias[col + 1];
            float v0 = acc[fm][fn][0] + b0;
            float v1 = acc[fm][fn][1] + b1;
            float v2 = acc[fm][fn][2] + b0;
            float v3 = acc[fm][fn][3] + b1;
            if (EPI == 2) {
                const float2 r0 = *(const float2*)(res + (size_t)row0 * N + col);
                const float2 r1 = *(const float2*)(res + (size_t)(row0 + 8) * N + col);
                v0 += r0.x; v1 += r0.y; v2 += r1.x; v3 += r1.y;
                *(float2*)(outF + (size_t)row0 * N + col)       = make_float2(v0, v1);
                *(float2*)(outF + (size_t)(row0 + 8) * N + col) = make_float2(v2, v3);
            }
            if (EPI == 1) {
                v0 = gelu_tanh(v0); v1 = gelu_tanh(v1);
                v2 = gelu_tanh(v2); v3 = gelu_tanh(v3);
                *(uint32_t*)(outH + (size_t)row0 * N + col) =
                    packh2(__float2half_rn(v0), __float2half_rn(v1));
                *(uint32_t*)(outH + (size_t)(row0 + 8) * N + col) =
                    packh2(__float2half_rn(v2), __float2half_rn(v3));
            }
            if (EPI == 3) {
                const int which = col / CC;
                const int cc = col - which * CC;
                const int hh = cc >> 6, d = cc & 63;
                const int b0r = row0 >> 11, t0r = row0 & 2047;
                const int b1r = (row0 + 8) >> 11, t1r = (row0 + 8) & 2047;
                const size_t base0 = ((size_t)(b0r * HH + hh) * TT + t0r) * 64 + d;
                const size_t base1 = ((size_t)(b1r * HH + hh) * TT + t1r) * 64 + d;
                const float sc = (which == 0) ? QSCALE : 1.0f;
                __half* o = (which == 0) ? outH : (which == 1) ? oks : ovs;
                *(uint32_t*)(o + base0) = packh2(__float2half_rn(v0 * sc), __float2half_rn(v1 * sc));
                *(uint32_t*)(o + base1) = packh2(__float2half_rn(v2 * sc), __float2half_rn(v3 * sc));
            }
        }
    }
}

// ================= single-term fp16 HMMA flash attention, 3-stage KV pipeline =============
// Q-tile 128 rows (8 warps x m16), K-tile 64, per-head layout [bh][T][64]. 1 CTA/SM.
// smem: Q 16K | 3 KV stages of (K 8K | V 8K)
#define ATT_SMEM 65536
__global__ __launch_bounds__(256, 1) void attn_mma(
    const __half* __restrict__ qq,
    const __half* __restrict__ kk, const __half* __restrict__ vv,
    __half* __restrict__ yy)
{
    extern __shared__ __align__(1024) char smem[];
    const uint32_t sb = smem_u32(smem);
    enum { Q_O = 0, KV0 = 16384, KV_STRIDE = 16384, K_O = 0, V_O = 8192 };

    const int t = threadIdx.x, lane = t & 31, wid = t >> 5;
    const int qt = (int)(gridDim.x - 1) - (int)blockIdx.x;   // big tiles first
    const int bh = blockIdx.y;
    const int qbase = qt * 128;
    const size_t hb = (size_t)bh * TT * 64;
    const int warpQ = wid * 16;

    // Q copy
    #pragma unroll
    for (int i = 0; i < 4; ++i) {
        const int idx = t + i * 256;
        const int row = idx >> 3, seg = idx & 7;
        const uint32_t so = SMEM_SWIZZLE_128B((uint32_t)(row * 128 + seg * 16));
        cp16(sb + Q_O + so, qq + hb + (size_t)(qbase + row) * 64 + seg * 8);
    }
    auto load_kv = [&](int buf, int kt) {
        const uint32_t dst = sb + KV0 + buf * KV_STRIDE;
        #pragma unroll
        for (int i = 0; i < 2; ++i) {
            const int idx = t + i * 256;
            const int row = idx >> 3, seg = idx & 7;
            const uint32_t so = SMEM_SWIZZLE_128B((uint32_t)(row * 128 + seg * 16));
            const size_t g = hb + (size_t)(kt * 64 + row) * 64 + seg * 8;
            cp16(dst + K_O + so, kk + g);
            cp16(dst + V_O + so, vv + g);
        }
    };
    const int nkt = 2 * qt + 2;
    load_kv(0, 0);
    CP_COMMIT();
    load_kv(1, 1);
    CP_COMMIT();

    uint32_t qa[4][4];
    float o[8][4];
    #pragma unroll
    for (int j = 0; j < 8; ++j)
        #pragma unroll
        for (int e = 0; e < 4; ++e) o[j][e] = 0.f;
    float m0r = -1e30f, m1r = -1e30f, l0r = 0.f, l1r = 0.f;

    int buf = 0;
    for (int kt = 0; kt < nkt; ++kt) {
        if (kt == nkt - 1) { CP_WAIT0(); } else { CP_WAIT1(); }
        __syncthreads();
        if (kt + 2 < nkt) {
            int nb = buf + 2; if (nb >= 3) nb -= 3;
            load_kv(nb, kt + 2);
            CP_COMMIT();
        }

        if (kt == 0) {
            const uint32_t qrow = (uint32_t)(warpQ + (lane & 15));
            const uint32_t qbyt = (uint32_t)((lane >> 4) * 16);
            #pragma unroll
            for (int s = 0; s < 4; ++s)
                ldm_x4(qa[s], sb + Q_O + SMEM_SWIZZLE_128B(qrow * 128 + s * 32 + qbyt));
        }
        const uint32_t st = sb + KV0 + buf * KV_STRIDE;

        // ---- S = Q16 K16^T ----
        float sacc[8][4];
        #pragma unroll
        for (int j = 0; j < 8; ++j) { sacc[j][0]=0.f; sacc[j][1]=0.f; sacc[j][2]=0.f; sacc[j][3]=0.f; }
        #pragma unroll
        for (int j = 0; j < 8; ++j) {
            const uint32_t krow = (uint32_t)(j * 8 + (lane & 7));
            const uint32_t kbyt = (uint32_t)(((lane >> 3) & 3) * 16);
            uint32_t kb0[4], kb1[4];
            ldm_x4(kb0, st + K_O + SMEM_SWIZZLE_128B(krow * 128 + kbyt));
            ldm_x4(kb1, st + K_O + SMEM_SWIZZLE_128B(krow * 128 + 64 + kbyt));
            mma_f16(sacc[j], qa[0], kb0 + 0); mma_f16(sacc[j], qa[1], kb0 + 2);
            mma_f16(sacc[j], qa[2], kb1 + 0); mma_f16(sacc[j], qa[3], kb1 + 2);
        }

        // ---- causal mask (last two K-tiles only) ----
        if (kt >= 2 * qt) {
            const int r0 = qbase + warpQ + (lane >> 2);
            #pragma unroll
            for (int j = 0; j < 8; ++j) {
                const int c = kt * 64 + j * 8 + (lane & 3) * 2;
                if (c     > r0)     sacc[j][0] = -1e30f;
                if (c + 1 > r0)     sacc[j][1] = -1e30f;
                if (c     > r0 + 8) sacc[j][2] = -1e30f;
                if (c + 1 > r0 + 8) sacc[j][3] = -1e30f;
            }
        }

        // ---- online softmax (base-2) ----
        float tm0 = -1e30f, tm1 = -1e30f;
        #pragma unroll
        for (int j = 0; j < 8; ++j) {
            tm0 = fmaxf(tm0, fmaxf(sacc[j][0], sacc[j][1]));
            tm1 = fmaxf(tm1, fmaxf(sacc[j][2], sacc[j][3]));
        }
        tm0 = fmaxf(tm0, __shfl_xor_sync(0xffffffffu, tm0, 1));
        tm0 = fmaxf(tm0, __shfl_xor_sync(0xffffffffu, tm0, 2));
        tm1 = fmaxf(tm1, __shfl_xor_sync(0xffffffffu, tm1, 1));
        tm1 = fmaxf(tm1, __shfl_xor_sync(0xffffffffu, tm1, 2));
        const float mn0 = fmaxf(m0r, tm0), mn1 = fmaxf(m1r, tm1);
        const float al0 = exp2f(m0r - mn0), al1 = exp2f(m1r - mn1);
        m0r = mn0; m1r = mn1;
        float rs0 = 0.f, rs1 = 0.f;
        #pragma unroll
        for (int j = 0; j < 8; ++j) {
            sacc[j][0] = exp2f(sacc[j][0] - mn0);
            sacc[j][1] = exp2f(sacc[j][1] - mn0);
            sacc[j][2] = exp2f(sacc[j][2] - mn1);
            sacc[j][3] = exp2f(sacc[j][3] - mn1);
            rs0 += sacc[j][0] + sacc[j][1];
            rs1 += sacc[j][2] + sacc[j][3];
        }
        rs0 += __shfl_xor_sync(0xffffffffu, rs0, 1);
        rs0 += __shfl_xor_sync(0xffffffffu, rs0, 2);
        rs1 += __shfl_xor_sync(0xffffffffu, rs1, 1);
        rs1 += __shfl_xor_sync(0xffffffffu, rs1, 2);
        l0r = l0r * al0 + rs0;
        l1r = l1r * al1 + rs1;
        #pragma unroll
        for (int j = 0; j < 8; ++j) {
            o[j][0] *= al0; o[j][1] *= al0; o[j][2] *= al1; o[j][3] *= al1;
        }

        // ---- P -> fp16 A-operand fragments ----
        uint32_t pa[4][4];
        #pragma unroll
        for (int s = 0; s < 4; ++s) {
            pa[s][0] = packh2(__float2half_rn(sacc[2*s][0]),   __float2half_rn(sacc[2*s][1]));
            pa[s][1] = packh2(__float2half_rn(sacc[2*s][2]),   __float2half_rn(sacc[2*s][3]));
            pa[s][2] = packh2(__float2half_rn(sacc[2*s+1][0]), __float2half_rn(sacc[2*s+1][1]));
            pa[s][3] = packh2(__float2half_rn(sacc[2*s+1][2]), __float2half_rn(sacc[2*s+1][3]));
        }

        // ---- O += P16 V16 (V^T via ldmatrix.trans) ----
        #pragma unroll
        for (int jp = 0; jp < 4; ++jp) {
            #pragma unroll
            for (int s = 0; s < 4; ++s) {
                const uint32_t vrow = (uint32_t)(s * 16 + (lane & 15));
                const uint32_t vbyt = (uint32_t)(jp * 32 + (lane >> 4) * 16);
                uint32_t vb[4];
                ldm_x4_trans(vb, st + V_O + SMEM_SWIZZLE_128B(vrow * 128 + vbyt));
                mma_f16(o[2*jp],     pa[s], vb + 0);
                mma_f16(o[2*jp + 1], pa[s], vb + 2);
            }
        }
        ++buf; if (buf >= 3) buf -= 3;
    }

    // ---- epilogue: normalize, write y (single fp16) ----
    const float inv0 = 1.0f / l0r, inv1 = 1.0f / l1r;
    const int b = bh / HH, h = bh - b * HH;
    const size_t row0 = (size_t)b * TT + qbase + warpQ + (lane >> 2);
    #pragma unroll
    for (int j = 0; j < 8; ++j) {
        const int col = h * 64 + j * 8 + (lane & 3) * 2;
        *(uint32_t*)(yy + row0 * CC + col) =
            packh2(__float2half_rn(o[j][0] * inv0), __float2half_rn(o[j][1] * inv0));
        *(uint32_t*)(yy + (row0 + 8) * CC + col) =
            packh2(__float2half_rn(o[j][2] * inv1), __float2half_rn(o[j][3] * inv1));
    }
}

// ================= launch =================
extern "C" void kernel_launch(void* const* d_in, const int* in_sizes, int n_in,
                              void* d_out, int out_size)
{
    const float* x       = (const float*)d_in[0];
    const float* ln1_g   = (const float*)d_in[1];
    const float* ln1_b   = (const float*)d_in[2];
    const float* w_attn  = (const float*)d_in[3];
    const float* b_attn  = (const float*)d_in[4];
    const float* w_aproj = (const float*)d_in[5];
    const float* b_aproj = (const float*)d_in[6];
    const float* ln2_g   = (const float*)d_in[7];
    const float* ln2_b   = (const float*)d_in[8];
    const float* w_fc    = (const float*)d_in[9];
    const float* b_fc    = (const float*)d_in[10];
    const float* w_mproj = (const float*)d_in[11];
    const float* b_mproj = (const float*)d_in[12];
    float* out = (float*)d_out;

    __half *h1,*y,*h2,*fc,*wq,*wa,*wf,*wm,*qs,*ks,*vs;
    float *x1;
    cudaGetSymbolAddress((void**)&h1, g_h1);
    cudaGetSymbolAddress((void**)&y,  g_y);
    cudaGetSymbolAddress((void**)&x1, g_x1);
    cudaGetSymbolAddress((void**)&h2, g_h2);
    cudaGetSymbolAddress((void**)&fc, g_fc);
    cudaGetSymbolAddress((void**)&wq, g_wq);
    cudaGetSymbolAddress((void**)&wa, g_wa);
    cudaGetSymbolAddress((void**)&wf, g_wf);
    cudaGetSymbolAddress((void**)&wm, g_wm);
    cudaGetSymbolAddress((void**)&qs, g_qs);
    cudaGetSymbolAddress((void**)&ks, g_ks);
    cudaGetSymbolAddress((void**)&vs, g_vs);

    cudaFuncSetAttribute(hmma_gemm<1>, cudaFuncAttributeMaxDynamicSharedMemorySize, GEMM_SMEM);
    cudaFuncSetAttribute(hmma_gemm<2>, cudaFuncAttributeMaxDynamicSharedMemorySize, GEMM_SMEM);
    cudaFuncSetAttribute(hmma_gemm<3>, cudaFuncAttributeMaxDynamicSharedMemorySize, GEMM_SMEM);
    cudaFuncSetAttribute(attn_mma,     cudaFuncAttributeMaxDynamicSharedMemorySize, ATT_SMEM);

    // 0) fused prep: weight transposes + LN1
    prep_kernel<<<7936, 256>>>(w_attn, w_aproj, w_fc, w_mproj,
                               wq, wa, wf, wm, x, ln1_g, ln1_b, h1);
    // 1) q/k/v = per-head(h1 @ w_attn + b_attn), Q scaled
    hmma_gemm<3><<<dim3(QKVC/128, NROWS/128), 256, GEMM_SMEM>>>(
        h1, wq, b_attn, nullptr, nullptr, qs, ks, vs, NROWS, QKVC, CC);
    // 2) y = attention
    attn_mma<<<dim3(TT/128, BB*HH), 256, ATT_SMEM>>>(qs, ks, vs, y);
    // 3) x1 = y @ w_aproj + b_aproj + x
    hmma_gemm<2><<<dim3(CC/128, NROWS/128), 256, GEMM_SMEM>>>(
        y, wa, b_aproj, x, x1, nullptr, nullptr, nullptr, NROWS, CC, CC);
    // 4) h2 = ln2(x1)
    ln_h_kernel<<<NROWS/8, 256>>>(x1, ln2_g, ln2_b, h2);
    // 5) fc = gelu(h2 @ w_fc + b_fc)
    hmma_gemm<1><<<dim3(FFC/128, NROWS/128), 256, GEMM_SMEM>>>(
        h2, wf, b_fc, nullptr, nullptr, fc, nullptr, nullptr, NROWS, FFC, CC);
    // 6) out = fc @ w_mproj + b_mproj + x1
    hmma_gemm<2><<<dim3(CC/128, NROWS/128), 256, GEMM_SMEM>>>(
        fc, wm, b_mproj, x1, out, nullptr, nullptr, nullptr, NROWS, CC, FFC);
}

// round 14
// speedup vs baseline: 1.0624x; 1.0624x over previous
#include <cuda_runtime.h>
#include <cuda_fp16.h>
#include <math.h>
#include <stdint.h>

// Problem constants
#define BB 4
#define TT 2048
#define CC 768
#define HH 12
#define DD 64
#define NROWS (BB*TT)          // 8192
#define QKVC (3*CC)            // 2304
#define FFC (4*CC)             // 3072

#define QSCALE (0.125f * 1.4426950408889634f)   // 1/sqrt(D) * log2(e)

// ================= scratch (allocation-free: __device__ globals) =================
__device__ __half g_h1[NROWS*CC];
__device__ __half g_y [NROWS*CC];
__device__ float  g_x1[NROWS*CC];
__device__ __half g_h2[NROWS*CC];
__device__ __half g_fc[NROWS*FFC];
__device__ __half g_wq[QKVC*CC];   // [N][K] K-major, single fp16
__device__ __half g_wa[CC*CC];
__device__ __half g_wf[FFC*CC];
__device__ __half g_wm[CC*FFC];
// per-head q/k/v: [b*H+h][T][64], single fp16 (Q pre-scaled)
__device__ __half g_qs[NROWS*CC];
__device__ __half g_ks[NROWS*CC];
__device__ __half g_vs[NROWS*CC];

__device__ __forceinline__ uint32_t packh2(__half a, __half b) {
    return (uint32_t)__half_as_ushort(a) | ((uint32_t)__half_as_ushort(b) << 16);
}
__device__ __forceinline__ uint32_t smem_u32(const void* p) {
    uint32_t a;
    asm("{ .reg .u64 t; cvta.to.shared.u64 t, %1; cvt.u32.u64 %0, t; }" : "=r"(a) : "l"(p));
    return a;
}
__device__ __forceinline__ void cp16(uint32_t saddr, const void* g) {
    asm volatile("cp.async.cg.shared.global [%0], [%1], 16;" :: "r"(saddr), "l"(g));
}
#define CP_COMMIT() asm volatile("cp.async.commit_group;" ::: "memory")
#define CP_WAIT1()  asm volatile("cp.async.wait_group 1;" ::: "memory")
#define CP_WAIT0()  asm volatile("cp.async.wait_group 0;" ::: "memory")

__device__ __forceinline__ void ldm_x4(uint32_t* r, uint32_t addr) {
    asm volatile("ldmatrix.sync.aligned.m8n8.x4.shared.b16 {%0,%1,%2,%3}, [%4];"
        : "=r"(r[0]), "=r"(r[1]), "=r"(r[2]), "=r"(r[3]) : "r"(addr));
}
__device__ __forceinline__ void ldm_x4_trans(uint32_t* r, uint32_t addr) {
    asm volatile("ldmatrix.sync.aligned.m8n8.x4.trans.shared.b16 {%0,%1,%2,%3}, [%4];"
        : "=r"(r[0]), "=r"(r[1]), "=r"(r[2]), "=r"(r[3]) : "r"(addr));
}
__device__ __forceinline__ void mma_f16(float* c, const uint32_t* a, const uint32_t* b) {
    asm volatile("mma.sync.aligned.m16n8k16.row.col.f32.f16.f16.f32 "
        "{%0,%1,%2,%3}, {%4,%5,%6,%7}, {%8,%9}, {%0,%1,%2,%3};"
        : "+f"(c[0]), "+f"(c[1]), "+f"(c[2]), "+f"(c[3])
        : "r"(a[0]), "r"(a[1]), "r"(a[2]), "r"(a[3]), "r"(b[0]), "r"(b[1]));
}
#define SMEM_SWIZZLE_128B(o) ((o) ^ (((o) >> 3) & 0x70))

// fp32 -> packed f16x2 (lo, hi)
__device__ __forceinline__ uint32_t f2h2(float lo, float hi) {
    uint32_t r;
    asm("cvt.rn.f16x2.f32 %0, %1, %2;" : "=r"(r) : "f"(hi), "f"(lo));
    return r;
}
// packed f16x2 exp2
__device__ __forceinline__ uint32_t h2ex2(uint32_t a) {
    uint32_t r;
    asm("ex2.approx.f16x2 %0, %1;" : "=r"(r) : "r"(a));
    return r;
}
__device__ __forceinline__ float ex2f(float a) {
    float r;
    asm("ex2.approx.ftz.f32 %0, %1;" : "=f"(r) : "f"(a));
    return r;
}
__device__ __forceinline__ float rcpf(float a) {
    float r;
    asm("rcp.approx.ftz.f32 %0, %1;" : "=f"(r) : "f"(a));
    return r;
}

// gelu(v) = v * sigmoid(2u), u = c*(v + 0.044715 v^3)  (tanh form, exp2-based)
__device__ __forceinline__ float gelu_tanh(float v) {
    const float c2 = 2.0f * 0.7978845608028654f * 1.4426950408889634f;  // 2*c*log2(e)
    float u2 = c2 * (v + 0.044715f * v * v * v);
    return v * (1.0f - rcpf(1.0f + ex2f(u2)));
}

// ================= device helpers: weight transpose tile + LN row-block =================
__device__ __forceinline__ void tsplit_tile(const float* __restrict__ w,
                                            __half* __restrict__ th,
                                            int K, int N, int bx, int by,
                                            float (*tile)[33])
{
    const int tx = threadIdx.x & 31, ty = threadIdx.x >> 5;   // 32x8
    const int n0 = bx * 32, k0 = by * 32;
    #pragma unroll
    for (int r = 0; r < 4; ++r)
        tile[ty + 8*r][tx] = w[(size_t)(k0 + ty + 8*r) * N + n0 + tx];
    __syncthreads();
    #pragma unroll
    for (int r = 0; r < 4; ++r)
        th[(size_t)(n0 + ty + 8*r) * K + k0 + tx] = __float2half_rn(tile[tx][ty + 8*r]);
}

__device__ __forceinline__ void ln_rows(const float* __restrict__ x,
                                        const float* __restrict__ g,
                                        const float* __restrict__ bt,
                                        __half* __restrict__ oh, int rowblk)
{
    const int row  = rowblk * 8 + (threadIdx.x >> 5);
    const int lane = threadIdx.x & 31;
    const float* xr = x + (size_t)row * CC;

    float4 v[6];
    float sum = 0.f;
    #pragma unroll
    for (int i = 0; i < 6; ++i) {
        v[i] = *(const float4*)(xr + lane*4 + i*128);
        sum += (v[i].x + v[i].y) + (v[i].z + v[i].w);
    }
    #pragma unroll
    for (int off = 16; off > 0; off >>= 1) sum += __shfl_xor_sync(0xffffffffu, sum, off);
    const float mu = sum * (1.0f/768.0f);
    float var = 0.f;
    #pragma unroll
    for (int i = 0; i < 6; ++i) {
        float dx;
        dx = v[i].x - mu; var += dx*dx;  dx = v[i].y - mu; var += dx*dx;
        dx = v[i].z - mu; var += dx*dx;  dx = v[i].w - mu; var += dx*dx;
    }
    #pragma unroll
    for (int off = 16; off > 0; off >>= 1) var += __shfl_xor_sync(0xffffffffu, var, off);
    const float rstd = rsqrtf(var * (1.0f/768.0f) + 1e-5f);

    #pragma unroll
    for (int i = 0; i < 6; ++i) {
        const int col = lane*4 + i*128;
        const float4 gg = *(const float4*)(g  + col);
        const float4 bb = *(const float4*)(bt + col);
        const float r0 = (v[i].x - mu)*rstd*gg.x + bb.x;
        const float r1 = (v[i].y - mu)*rstd*gg.y + bb.y;
        const float r2 = (v[i].z - mu)*rstd*gg.z + bb.z;
        const float r3 = (v[i].w - mu)*rstd*gg.w + bb.w;
        const size_t o = (size_t)row * CC + col;
        *(uint2*)(oh + o) = make_uint2(
            packh2(__float2half_rn(r0), __float2half_rn(r1)),
            packh2(__float2half_rn(r2), __float2half_rn(r3)));
    }
}

// ================= fused prep: 4 weight transposes + LN1, one launch =================
__global__ __launch_bounds__(256) void prep_kernel(
    const float* __restrict__ w_attn, const float* __restrict__ w_aproj,
    const float* __restrict__ w_fc,   const float* __restrict__ w_mproj,
    __half* __restrict__ wq, __half* __restrict__ wa,
    __half* __restrict__ wf, __half* __restrict__ wm,
    const float* __restrict__ x, const float* __restrict__ ln1_g,
    const float* __restrict__ ln1_b, __half* __restrict__ h1)
{
    __shared__ float tile[32][33];
    int id = blockIdx.x;
    if (id < 1728) {
        tsplit_tile(w_attn, wq, CC, QKVC, id % 72, id / 72, tile);
    } else if (id < 2304) {
        id -= 1728;
        tsplit_tile(w_aproj, wa, CC, CC, id % 24, id / 24, tile);
    } else if (id < 4608) {
        id -= 2304;
        tsplit_tile(w_fc, wf, CC, FFC, id % 96, id / 96, tile);
    } else if (id < 6912) {
        id -= 4608;
        tsplit_tile(w_mproj, wm, FFC, CC, id % 24, id / 24, tile);
    } else {
        ln_rows(x, ln1_g, ln1_b, h1, id - 6912);
    }
}

// ================= LayerNorm -> single fp16 (LN2) =================
__global__ __launch_bounds__(256) void ln_h_kernel(const float* __restrict__ x,
                                                   const float* __restrict__ g,
                                                   const float* __restrict__ bt,
                                                   __half* __restrict__ oh)
{
    ln_rows(x, g, bt, oh, blockIdx.x);
}

// ================= single-term fp16 HMMA GEMM (R8 core), 2-stage, 2 CTAs/SM ==============
// D[M,N] = A16[M,K] @ W16^T + bias, epilogues:
// EPI 1 = bias+gelu -> fp16; EPI 2 = bias+res -> fp32; EPI 3 = qkv per-head
#define TEN_BYTES 18432              // 128 rows * 72 elems * 2B
#define STAGE_BYTES (2*TEN_BYTES)    // A, B = 36864
#define GEMM_SMEM (2*STAGE_BYTES)    // 73728 -> 2 CTAs/SM
#define ROWB 144

template<int EPI>
__global__ __launch_bounds__(256, 2) void hmma_gemm(
    const __half* __restrict__ Aa,
    const __half* __restrict__ Bw,
    const float* __restrict__ bias, const float* __restrict__ res,
    float* __restrict__ outF, __half* __restrict__ outH,
    __half* __restrict__ oks, __half* __restrict__ ovs,
    int M, int N, int K)
{
    extern __shared__ __align__(1024) char smem[];
    const uint32_t sb = smem_u32(smem);

    const int t    = threadIdx.x;
    const int lane = t & 31;
    const int wid  = t >> 5;
    const int warp_m = wid >> 2;
    const int warp_n = wid & 3;
    const int n0 = blockIdx.x * 128;
    const int m0 = blockIdx.y * 128;

    float acc[4][4][4];
    #pragma unroll
    for (int i = 0; i < 4; ++i)
        #pragma unroll
        for (int j = 0; j < 4; ++j)
            #pragma unroll
            for (int e = 0; e < 4; ++e) acc[i][j][e] = 0.f;

    const uint32_t aBase = sb + 0*TEN_BYTES + (uint32_t)(warp_m*64 + (lane & 15)) * ROWB + (lane >> 4) * 16;
    const uint32_t bRow   = (uint32_t)((lane & 7) + ((lane >> 4) << 3));
    const uint32_t bCol16 = (uint32_t)(((lane >> 3) & 1) * 16);
    const uint32_t bBase = sb + 1*TEN_BYTES + (uint32_t)(warp_n*32 + bRow) * ROWB + bCol16;

    const int nch = K >> 6;

    auto load_stage = [&](int buf, int k0) {
        const uint32_t dst = sb + buf * STAGE_BYTES;
        #pragma unroll
        for (int i = 0; i < 4; ++i) {
            const int idx = i * 256 + t;
            const int row = idx >> 3;
            const int seg = idx & 7;
            const uint32_t so = (uint32_t)row * ROWB + seg * 16;
            cp16(dst + 0*TEN_BYTES + so, Aa + (size_t)(m0 + row) * K + k0 + seg * 8);
            cp16(dst + 1*TEN_BYTES + so, Bw + (size_t)(n0 + row) * K + k0 + seg * 8);
        }
    };

    load_stage(0, 0);
    CP_COMMIT();

    int buf = 0;
    for (int ch = 0; ch < nch; ++ch) {
        if (ch + 1 < nch) {
            load_stage(buf ^ 1, (ch + 1) << 6);
            CP_COMMIT();
            CP_WAIT1();
        } else {
            CP_WAIT0();
        }
        __syncthreads();

        const uint32_t st = (uint32_t)buf * STAGE_BYTES;
        #pragma unroll
        for (int ks = 0; ks < 4; ++ks) {
            const uint32_t kb = ks * 32;
            uint32_t af[4][4];
            #pragma unroll
            for (int fm = 0; fm < 4; ++fm)
                ldm_x4(af[fm], aBase + st + fm * (16 * ROWB) + kb);
            uint32_t bf[2][4];
            #pragma unroll
            for (int p = 0; p < 2; ++p)
                ldm_x4(bf[p], bBase + st + p * (16 * ROWB) + kb);
            #pragma unroll
            for (int fm = 0; fm < 4; ++fm)
                #pragma unroll
                for (int fn = 0; fn < 4; ++fn)
                    mma_f16(acc[fm][fn], af[fm], bf[fn >> 1] + (fn & 1) * 2);
        }
        __syncthreads();
        buf ^= 1;
    }

    #pragma unroll
    for (int fm = 0; fm < 4; ++fm) {
        const int row0 = m0 + warp_m*64 + fm*16 + (lane >> 2);
        #pragma unroll
        for (int fn = 0; fn < 4; ++fn) {
            const int col = n0 + warp_n*32 + fn*8 + (lane & 3)*2;
            const float b0 = bias[col], b1 = bias[col + 1];
            float v0 = acc[fm][fn][0] + b0;
            float v1 = acc[fm][fn][1] + b1;
            float v2 = acc[fm][fn][2] + b0;
            float v3 = acc[fm][fn][3] + b1;
            if (EPI == 2) {
                const float2 r0 = *(const float2*)(res + (size_t)row0 * N + col);
                const float2 r1 = *(const float2*)(res + (size_t)(row0 + 8) * N + col);
                v0 += r0.x; v1 += r0.y; v2 += r1.x; v3 += r1.y;
                *(float2*)(outF + (size_t)row0 * N + col)       = make_float2(v0, v1);
                *(float2*)(outF + (size_t)(row0 + 8) * N + col) = make_float2(v2, v3);
            }
            if (EPI == 1) {
                v0 = gelu_tanh(v0); v1 = gelu_tanh(v1);
                v2 = gelu_tanh(v2); v3 = gelu_tanh(v3);
                *(uint32_t*)(outH + (size_t)row0 * N + col) =
                    packh2(__float2half_rn(v0), __float2half_rn(v1));
                *(uint32_t*)(outH + (size_t)(row0 + 8) * N + col) =
                    packh2(__float2half_rn(v2), __float2half_rn(v3));
            }
            if (EPI == 3) {
                const int which = col / CC;
                const int cc = col - which * CC;
                const int hh = cc >> 6, d = cc & 63;
                const int b0r = row0 >> 11, t0r = row0 & 2047;
                const int b1r = (row0 + 8) >> 11, t1r = (row0 + 8) & 2047;
                const size_t base0 = ((size_t)(b0r * HH + hh) * TT + t0r) * 64 + d;
                const size_t base1 = ((size_t)(b1r * HH + hh) * TT + t1r) * 64 + d;
                const float sc = (which == 0) ? QSCALE : 1.0f;
                __half* o = (which == 0) ? outH : (which == 1) ? oks : ovs;
                *(uint32_t*)(o + base0) = packh2(__float2half_rn(v0 * sc), __float2half_rn(v1 * sc));
                *(uint32_t*)(o + base1) = packh2(__float2half_rn(v2 * sc), __float2half_rn(v3 * sc));
            }
        }
    }
}

// ================= fp16 HMMA flash attention, f16x2 softmax + ones-MMA row sums ==========
// Q-tile 128 rows (8 warps x m16), K-tile 64, per-head layout [bh][T][64]. 1 CTA/SM.
// smem: Q 16K | 3 KV stages of (K 8K | V 8K)
#define ATT_SMEM 65536
__global__ __launch_bounds__(256, 1) void attn_mma(
    const __half* __restrict__ qq,
    const __half* __restrict__ kk, const __half* __restrict__ vv,
    __half* __restrict__ yy)
{
    extern __shared__ __align__(1024) char smem[];
    const uint32_t sb = smem_u32(smem);
    enum { Q_O = 0, KV0 = 16384, KV_STRIDE = 16384, K_O = 0, V_O = 8192 };

    const int t = threadIdx.x, lane = t & 31, wid = t >> 5;
    const int qt = (int)(gridDim.x - 1) - (int)blockIdx.x;   // big tiles first
    const int bh = blockIdx.y;
    const int qbase = qt * 128;
    const size_t hb = (size_t)bh * TT * 64;
    const int warpQ = wid * 16;

    // Q copy
    #pragma unroll
    for (int i = 0; i < 4; ++i) {
        const int idx = t + i * 256;
        const int row = idx >> 3, seg = idx & 7;
        const uint32_t so = SMEM_SWIZZLE_128B((uint32_t)(row * 128 + seg * 16));
        cp16(sb + Q_O + so, qq + hb + (size_t)(qbase + row) * 64 + seg * 8);
    }
    auto load_kv = [&](int buf, int kt) {
        const uint32_t dst = sb + KV0 + buf * KV_STRIDE;
        #pragma unroll
        for (int i = 0; i < 2; ++i) {
            const int idx = t + i * 256;
            const int row = idx >> 3, seg = idx & 7;
            const uint32_t so = SMEM_SWIZZLE_128B((uint32_t)(row * 128 + seg * 16));
            const size_t g = hb + (size_t)(kt * 64 + row) * 64 + seg * 8;
            cp16(dst + K_O + so, kk + g);
            cp16(dst + V_O + so, vv + g);
        }
    };
    const int nkt = 2 * qt + 2;
    load_kv(0, 0);
    CP_COMMIT();
    load_kv(1, 1);
    CP_COMMIT();

    uint32_t qa[4][4];
    float o[8][4];
    #pragma unroll
    for (int j = 0; j < 8; ++j)
        #pragma unroll
        for (int e = 0; e < 4; ++e) o[j][e] = 0.f;
    float m0r = -1e30f, m1r = -1e30f, l0r = 0.f, l1r = 0.f;

    const uint32_t ones2b[2] = {0x3C003C00u, 0x3C003C00u};   // fp16 {1,1} B fragment

    int buf = 0;
    for (int kt = 0; kt < nkt; ++kt) {
        if (kt == nkt - 1) { CP_WAIT0(); } else { CP_WAIT1(); }
        __syncthreads();
        if (kt + 2 < nkt) {
            int nb = buf + 2; if (nb >= 3) nb -= 3;
            load_kv(nb, kt + 2);
            CP_COMMIT();
        }

        if (kt == 0) {
            const uint32_t qrow = (uint32_t)(warpQ + (lane & 15));
            const uint32_t qbyt = (uint32_t)((lane >> 4) * 16);
            #pragma unroll
            for (int s = 0; s < 4; ++s)
                ldm_x4(qa[s], sb + Q_O + SMEM_SWIZZLE_128B(qrow * 128 + s * 32 + qbyt));
        }
        const uint32_t st = sb + KV0 + buf * KV_STRIDE;

        // ---- S = Q16 K16^T ----
        float sacc[8][4];
        #pragma unroll
        for (int j = 0; j < 8; ++j) { sacc[j][0]=0.f; sacc[j][1]=0.f; sacc[j][2]=0.f; sacc[j][3]=0.f; }
        #pragma unroll
        for (int j = 0; j < 8; ++j) {
            const uint32_t krow = (uint32_t)(j * 8 + (lane & 7));
            const uint32_t kbyt = (uint32_t)(((lane >> 3) & 3) * 16);
            uint32_t kb0[4], kb1[4];
            ldm_x4(kb0, st + K_O + SMEM_SWIZZLE_128B(krow * 128 + kbyt));
            ldm_x4(kb1, st + K_O + SMEM_SWIZZLE_128B(krow * 128 + 64 + kbyt));
            mma_f16(sacc[j], qa[0], kb0 + 0); mma_f16(sacc[j], qa[1], kb0 + 2);
            mma_f16(sacc[j], qa[2], kb1 + 0); mma_f16(sacc[j], qa[3], kb1 + 2);
        }

        // ---- causal mask (last two K-tiles only) ----
        if (kt >= 2 * qt) {
            const int r0 = qbase + warpQ + (lane >> 2);
            #pragma unroll
            for (int j = 0; j < 8; ++j) {
                const int c = kt * 64 + j * 8 + (lane & 3) * 2;
                if (c     > r0)     sacc[j][0] = -1e30f;
                if (c + 1 > r0)     sacc[j][1] = -1e30f;
                if (c     > r0 + 8) sacc[j][2] = -1e30f;
                if (c + 1 > r0 + 8) sacc[j][3] = -1e30f;
            }
        }

        // ---- online softmax (base-2): max in fp32, exp in f16x2, row sums via ones-MMA ----
        float tm0 = -1e30f, tm1 = -1e30f;
        #pragma unroll
        for (int j = 0; j < 8; ++j) {
            tm0 = fmaxf(tm0, fmaxf(sacc[j][0], sacc[j][1]));
            tm1 = fmaxf(tm1, fmaxf(sacc[j][2], sacc[j][3]));
        }
        tm0 = fmaxf(tm0, __shfl_xor_sync(0xffffffffu, tm0, 1));
        tm0 = fmaxf(tm0, __shfl_xor_sync(0xffffffffu, tm0, 2));
        tm1 = fmaxf(tm1, __shfl_xor_sync(0xffffffffu, tm1, 1));
        tm1 = fmaxf(tm1, __shfl_xor_sync(0xffffffffu, tm1, 2));
        const float mn0 = fmaxf(m0r, tm0), mn1 = fmaxf(m1r, tm1);
        const float al0 = ex2f(m0r - mn0), al1 = ex2f(m1r - mn1);
        m0r = mn0; m1r = mn1;

        uint32_t pa[4][4];
        float rsacc[4] = {0.f, 0.f, 0.f, 0.f};
        #pragma unroll
        for (int s = 0; s < 4; ++s) {
            pa[s][0] = h2ex2(f2h2(sacc[2*s][0]   - mn0, sacc[2*s][1]   - mn0));
            pa[s][1] = h2ex2(f2h2(sacc[2*s][2]   - mn1, sacc[2*s][3]   - mn1));
            pa[s][2] = h2ex2(f2h2(sacc[2*s+1][0] - mn0, sacc[2*s+1][1] - mn0));
            pa[s][3] = h2ex2(f2h2(sacc[2*s+1][2] - mn1, sacc[2*s+1][3] - mn1));
            mma_f16(rsacc, pa[s], ones2b);   // row sums: every n col identical
        }
        l0r = l0r * al0 + rsacc[0];
        l1r = l1r * al1 + rsacc[2];
        #pragma unroll
        for (int j = 0; j < 8; ++j) {
            o[j][0] *= al0; o[j][1] *= al0; o[j][2] *= al1; o[j][3] *= al1;
        }

        // ---- O += P16 V16 (V^T via ldmatrix.trans) ----
        #pragma unroll
        for (int jp = 0; jp < 4; ++jp) {
            #pragma unroll
            for (int s = 0; s < 4; ++s) {
                const uint32_t vrow = (uint32_t)(s * 16 + (lane & 15));
                const uint32_t vbyt = (uint32_t)(jp * 32 + (lane >> 4) * 16);
                uint32_t vb[4];
                ldm_x4_trans(vb, st + V_O + SMEM_SWIZZLE_128B(vrow * 128 + vbyt));
                mma_f16(o[2*jp],     pa[s], vb + 0);
                mma_f16(o[2*jp + 1], pa[s], vb + 2);
            }
        }
        ++buf; if (buf >= 3) buf -= 3;
    }

    // ---- epilogue: normalize, write y (single fp16) ----
    const float inv0 = 1.0f / l0r, inv1 = 1.0f / l1r;
    const int b = bh / HH, h = bh - b * HH;
    const size_t row0 = (size_t)b * TT + qbase + warpQ + (lane >> 2);
    #pragma unroll
    for (int j = 0; j < 8; ++j) {
        const int col = h * 64 + j * 8 + (lane & 3) * 2;
        *(uint32_t*)(yy + row0 * CC + col) =
            packh2(__float2half_rn(o[j][0] * inv0), __float2half_rn(o[j][1] * inv0));
        *(uint32_t*)(yy + (row0 + 8) * CC + col) =
            packh2(__float2half_rn(o[j][2] * inv1), __float2half_rn(o[j][3] * inv1));
    }
}

// ================= launch =================
extern "C" void kernel_launch(void* const* d_in, const int* in_sizes, int n_in,
                              void* d_out, int out_size)
{
    const float* x       = (const float*)d_in[0];
    const float* ln1_g   = (const float*)d_in[1];
    const float* ln1_b   = (const float*)d_in[2];
    const float* w_attn  = (const float*)d_in[3];
    const float* b_attn  = (const float*)d_in[4];
    const float* w_aproj = (const float*)d_in[5];
    const float* b_aproj = (const float*)d_in[6];
    const float* ln2_g   = (const float*)d_in[7];
    const float* ln2_b   = (const float*)d_in[8];
    const float* w_fc    = (const float*)d_in[9];
    const float* b_fc    = (const float*)d_in[10];
    const float* w_mproj = (const float*)d_in[11];
    const float* b_mproj = (const float*)d_in[12];
    float* out = (float*)d_out;

    __half *h1,*y,*h2,*fc,*wq,*wa,*wf,*wm,*qs,*ks,*vs;
    float *x1;
    cudaGetSymbolAddress((void**)&h1, g_h1);
    cudaGetSymbolAddress((void**)&y,  g_y);
    cudaGetSymbolAddress((void**)&x1, g_x1);
    cudaGetSymbolAddress((void**)&h2, g_h2);
    cudaGetSymbolAddress((void**)&fc, g_fc);
    cudaGetSymbolAddress((void**)&wq, g_wq);
    cudaGetSymbolAddress((void**)&wa, g_wa);
    cudaGetSymbolAddress((void**)&wf, g_wf);
    cudaGetSymbolAddress((void**)&wm, g_wm);
    cudaGetSymbolAddress((void**)&qs, g_qs);
    cudaGetSymbolAddress((void**)&ks, g_ks);
    cudaGetSymbolAddress((void**)&vs, g_vs);

    cudaFuncSetAttribute(hmma_gemm<1>, cudaFuncAttributeMaxDynamicSharedMemorySize, GEMM_SMEM);
    cudaFuncSetAttribute(hmma_gemm<2>, cudaFuncAttributeMaxDynamicSharedMemorySize, GEMM_SMEM);
    cudaFuncSetAttribute(hmma_gemm<3>, cudaFuncAttributeMaxDynamicSharedMemorySize, GEMM_SMEM);
    cudaFuncSetAttribute(attn_mma,     cudaFuncAttributeMaxDynamicSharedMemorySize, ATT_SMEM);

    // 0) fused prep: weight transposes + LN1
    prep_kernel<<<7936, 256>>>(w_attn, w_aproj, w_fc, w_mproj,
                               wq, wa, wf, wm, x, ln1_g, ln1_b, h1);
    // 1) q/k/v = per-head(h1 @ w_attn + b_attn), Q scaled
    hmma_gemm<3><<<dim3(QKVC/128, NROWS/128), 256, GEMM_SMEM>>>(
        h1, wq, b_attn, nullptr, nullptr, qs, ks, vs, NROWS, QKVC, CC);
    // 2) y = attention
    attn_mma<<<dim3(TT/128, BB*HH), 256, ATT_SMEM>>>(qs, ks, vs, y);
    // 3) x1 = y @ w_aproj + b_aproj + x
    hmma_gemm<2><<<dim3(CC/128, NROWS/128), 256, GEMM_SMEM>>>(
        y, wa, b_aproj, x, x1, nullptr, nullptr, nullptr, NROWS, CC, CC);
    // 4) h2 = ln2(x1)
    ln_h_kernel<<<NROWS/8, 256>>>(x1, ln2_g, ln2_b, h2);
    // 5) fc = gelu(h2 @ w_fc + b_fc)
    hmma_gemm<1><<<dim3(FFC/128, NROWS/128), 256, GEMM_SMEM>>>(
        h2, wf, b_fc, nullptr, nullptr, fc, nullptr, nullptr, NROWS, FFC, CC);
    // 6) out = fc @ w_mproj + b_mproj + x1
    hmma_gemm<2><<<dim3(CC/128, NROWS/128), 256, GEMM_SMEM>>>(
        fc, wm, b_mproj, x1, out, nullptr, nullptr, nullptr, NROWS, CC, FFC);
}

// round 15
// speedup vs baseline: 1.0680x; 1.0053x over previous
#include <cuda_runtime.h>
#include <cuda_fp16.h>
#include <math.h>
#include <stdint.h>

// Problem constants
#define BB 4
#define TT 2048
#define CC 768
#define HH 12
#define DD 64
#define NROWS (BB*TT)          // 8192
#define QKVC (3*CC)            // 2304
#define FFC (4*CC)             // 3072

#define QSCALE (0.125f * 1.4426950408889634f)   // 1/sqrt(D) * log2(e)

// ================= scratch (allocation-free: __device__ globals) =================
__device__ __half g_h1[NROWS*CC];
__device__ __half g_y [NROWS*CC];
__device__ float  g_x1[NROWS*CC];
__device__ __half g_h2[NROWS*CC];
__device__ __half g_fc[NROWS*FFC];
__device__ __half g_wq[QKVC*CC];   // [N][K] K-major, single fp16
__device__ __half g_wa[CC*CC];
__device__ __half g_wf[FFC*CC];
__device__ __half g_wm[CC*FFC];
// per-head q/k/v: [b*H+h][T][64], single fp16 (Q pre-scaled)
__device__ __half g_qs[NROWS*CC];
__device__ __half g_ks[NROWS*CC];
__device__ __half g_vs[NROWS*CC];

__device__ __forceinline__ uint32_t packh2(__half a, __half b) {
    return (uint32_t)__half_as_ushort(a) | ((uint32_t)__half_as_ushort(b) << 16);
}
__device__ __forceinline__ uint32_t smem_u32(const void* p) {
    uint32_t a;
    asm("{ .reg .u64 t; cvta.to.shared.u64 t, %1; cvt.u32.u64 %0, t; }" : "=r"(a) : "l"(p));
    return a;
}
__device__ __forceinline__ void cp16(uint32_t saddr, const void* g) {
    asm volatile("cp.async.cg.shared.global [%0], [%1], 16;" :: "r"(saddr), "l"(g));
}
#define CP_COMMIT() asm volatile("cp.async.commit_group;" ::: "memory")
#define CP_WAIT1()  asm volatile("cp.async.wait_group 1;" ::: "memory")
#define CP_WAIT0()  asm volatile("cp.async.wait_group 0;" ::: "memory")

__device__ __forceinline__ void ldm_x4(uint32_t* r, uint32_t addr) {
    asm volatile("ldmatrix.sync.aligned.m8n8.x4.shared.b16 {%0,%1,%2,%3}, [%4];"
        : "=r"(r[0]), "=r"(r[1]), "=r"(r[2]), "=r"(r[3]) : "r"(addr));
}
__device__ __forceinline__ void ldm_x4_trans(uint32_t* r, uint32_t addr) {
    asm volatile("ldmatrix.sync.aligned.m8n8.x4.trans.shared.b16 {%0,%1,%2,%3}, [%4];"
        : "=r"(r[0]), "=r"(r[1]), "=r"(r[2]), "=r"(r[3]) : "r"(addr));
}
__device__ __forceinline__ void mma_f16(float* c, const uint32_t* a, const uint32_t* b) {
    asm volatile("mma.sync.aligned.m16n8k16.row.col.f32.f16.f16.f32 "
        "{%0,%1,%2,%3}, {%4,%5,%6,%7}, {%8,%9}, {%0,%1,%2,%3};"
        : "+f"(c[0]), "+f"(c[1]), "+f"(c[2]), "+f"(c[3])
        : "r"(a[0]), "r"(a[1]), "r"(a[2]), "r"(a[3]), "r"(b[0]), "r"(b[1]));
}
#define SMEM_SWIZZLE_128B(o) ((o) ^ (((o) >> 3) & 0x70))

// fp32 -> packed f16x2 (lo, hi)
__device__ __forceinline__ uint32_t f2h2(float lo, float hi) {
    uint32_t r;
    asm("cvt.rn.f16x2.f32 %0, %1, %2;" : "=r"(r) : "f"(hi), "f"(lo));
    return r;
}
// packed f16x2 exp2
__device__ __forceinline__ uint32_t h2ex2(uint32_t a) {
    uint32_t r;
    asm("ex2.approx.f16x2 %0, %1;" : "=r"(r) : "r"(a));
    return r;
}
__device__ __forceinline__ float ex2f(float a) {
    float r;
    asm("ex2.approx.ftz.f32 %0, %1;" : "=f"(r) : "f"(a));
    return r;
}
__device__ __forceinline__ float rcpf(float a) {
    float r;
    asm("rcp.approx.ftz.f32 %0, %1;" : "=f"(r) : "f"(a));
    return r;
}

// gelu(v) = v * sigmoid(2u), u = c*(v + 0.044715 v^3)  (tanh form, exp2-based)
__device__ __forceinline__ float gelu_tanh(float v) {
    const float c2 = 2.0f * 0.7978845608028654f * 1.4426950408889634f;  // 2*c*log2(e)
    float u2 = c2 * (v + 0.044715f * v * v * v);
    return v * (1.0f - rcpf(1.0f + ex2f(u2)));
}

// ================= device helpers: weight transpose tile + LN row-block =================
__device__ __forceinline__ void tsplit_tile(const float* __restrict__ w,
                                            __half* __restrict__ th,
                                            int K, int N, int bx, int by,
                                            float (*tile)[33])
{
    const int tx = threadIdx.x & 31, ty = threadIdx.x >> 5;   // 32x8
    const int n0 = bx * 32, k0 = by * 32;
    #pragma unroll
    for (int r = 0; r < 4; ++r)
        tile[ty + 8*r][tx] = w[(size_t)(k0 + ty + 8*r) * N + n0 + tx];
    __syncthreads();
    #pragma unroll
    for (int r = 0; r < 4; ++r)
        th[(size_t)(n0 + ty + 8*r) * K + k0 + tx] = __float2half_rn(tile[tx][ty + 8*r]);
}

__device__ __forceinline__ void ln_rows(const float* __restrict__ x,
                                        const float* __restrict__ g,
                                        const float* __restrict__ bt,
                                        __half* __restrict__ oh, int rowblk)
{
    const int row  = rowblk * 8 + (threadIdx.x >> 5);
    const int lane = threadIdx.x & 31;
    const float* xr = x + (size_t)row * CC;

    float4 v[6];
    float sum = 0.f;
    #pragma unroll
    for (int i = 0; i < 6; ++i) {
        v[i] = *(const float4*)(xr + lane*4 + i*128);
        sum += (v[i].x + v[i].y) + (v[i].z + v[i].w);
    }
    #pragma unroll
    for (int off = 16; off > 0; off >>= 1) sum += __shfl_xor_sync(0xffffffffu, sum, off);
    const float mu = sum * (1.0f/768.0f);
    float var = 0.f;
    #pragma unroll
    for (int i = 0; i < 6; ++i) {
        float dx;
        dx = v[i].x - mu; var += dx*dx;  dx = v[i].y - mu; var += dx*dx;
        dx = v[i].z - mu; var += dx*dx;  dx = v[i].w - mu; var += dx*dx;
    }
    #pragma unroll
    for (int off = 16; off > 0; off >>= 1) var += __shfl_xor_sync(0xffffffffu, var, off);
    const float rstd = rsqrtf(var * (1.0f/768.0f) + 1e-5f);

    #pragma unroll
    for (int i = 0; i < 6; ++i) {
        const int col = lane*4 + i*128;
        const float4 gg = *(const float4*)(g  + col);
        const float4 bb = *(const float4*)(bt + col);
        const float r0 = (v[i].x - mu)*rstd*gg.x + bb.x;
        const float r1 = (v[i].y - mu)*rstd*gg.y + bb.y;
        const float r2 = (v[i].z - mu)*rstd*gg.z + bb.z;
        const float r3 = (v[i].w - mu)*rstd*gg.w + bb.w;
        const size_t o = (size_t)row * CC + col;
        *(uint2*)(oh + o) = make_uint2(
            packh2(__float2half_rn(r0), __float2half_rn(r1)),
            packh2(__float2half_rn(r2), __float2half_rn(r3)));
    }
}

// ================= fused prep: 4 weight transposes + LN1, one launch =================
__global__ __launch_bounds__(256) void prep_kernel(
    const float* __restrict__ w_attn, const float* __restrict__ w_aproj,
    const float* __restrict__ w_fc,   const float* __restrict__ w_mproj,
    __half* __restrict__ wq, __half* __restrict__ wa,
    __half* __restrict__ wf, __half* __restrict__ wm,
    const float* __restrict__ x, const float* __restrict__ ln1_g,
    const float* __restrict__ ln1_b, __half* __restrict__ h1)
{
    __shared__ float tile[32][33];
    int id = blockIdx.x;
    if (id < 1728) {
        tsplit_tile(w_attn, wq, CC, QKVC, id % 72, id / 72, tile);
    } else if (id < 2304) {
        id -= 1728;
        tsplit_tile(w_aproj, wa, CC, CC, id % 24, id / 24, tile);
    } else if (id < 4608) {
        id -= 2304;
        tsplit_tile(w_fc, wf, CC, FFC, id % 96, id / 96, tile);
    } else if (id < 6912) {
        id -= 4608;
        tsplit_tile(w_mproj, wm, FFC, CC, id % 24, id / 24, tile);
    } else {
        ln_rows(x, ln1_g, ln1_b, h1, id - 6912);
    }
}

// ================= LayerNorm -> single fp16 (LN2) =================
__global__ __launch_bounds__(256) void ln_h_kernel(const float* __restrict__ x,
                                                   const float* __restrict__ g,
                                                   const float* __restrict__ bt,
                                                   __half* __restrict__ oh)
{
    ln_rows(x, g, bt, oh, blockIdx.x);
}

// ================= single-term fp16 HMMA GEMM (R8 core), 2-stage, 2 CTAs/SM ==============
// D[M,N] = A16[M,K] @ W16^T + bias, epilogues:
// EPI 1 = bias+gelu -> fp16; EPI 2 = bias+res -> fp32; EPI 3 = qkv per-head
#define TEN_BYTES 18432              // 128 rows * 72 elems * 2B
#define STAGE_BYTES (2*TEN_BYTES)    // A, B = 36864
#define GEMM_SMEM (2*STAGE_BYTES)    // 73728 -> 2 CTAs/SM
#define ROWB 144

template<int EPI>
__global__ __launch_bounds__(256, 2) void hmma_gemm(
    const __half* __restrict__ Aa,
    const __half* __restrict__ Bw,
    const float* __restrict__ bias, const float* __restrict__ res,
    float* __restrict__ outF, __half* __restrict__ outH,
    __half* __restrict__ oks, __half* __restrict__ ovs,
    int M, int N, int K)
{
    extern __shared__ __align__(1024) char smem[];
    const uint32_t sb = smem_u32(smem);

    const int t    = threadIdx.x;
    const int lane = t & 31;
    const int wid  = t >> 5;
    const int warp_m = wid >> 2;
    const int warp_n = wid & 3;
    const int n0 = blockIdx.x * 128;
    const int m0 = blockIdx.y * 128;

    float acc[4][4][4];
    #pragma unroll
    for (int i = 0; i < 4; ++i)
        #pragma unroll
        for (int j = 0; j < 4; ++j)
            #pragma unroll
            for (int e = 0; e < 4; ++e) acc[i][j][e] = 0.f;

    const uint32_t aBase = sb + 0*TEN_BYTES + (uint32_t)(warp_m*64 + (lane & 15)) * ROWB + (lane >> 4) * 16;
    const uint32_t bRow   = (uint32_t)((lane & 7) + ((lane >> 4) << 3));
    const uint32_t bCol16 = (uint32_t)(((lane >> 3) & 1) * 16);
    const uint32_t bBase = sb + 1*TEN_BYTES + (uint32_t)(warp_n*32 + bRow) * ROWB + bCol16;

    const int nch = K >> 6;

    auto load_stage = [&](int buf, int k0) {
        const uint32_t dst = sb + buf * STAGE_BYTES;
        #pragma unroll
        for (int i = 0; i < 4; ++i) {
            const int idx = i * 256 + t;
            const int row = idx >> 3;
            const int seg = idx & 7;
            const uint32_t so = (uint32_t)row * ROWB + seg * 16;
            cp16(dst + 0*TEN_BYTES + so, Aa + (size_t)(m0 + row) * K + k0 + seg * 8);
            cp16(dst + 1*TEN_BYTES + so, Bw + (size_t)(n0 + row) * K + k0 + seg * 8);
        }
    };

    load_stage(0, 0);
    CP_COMMIT();

    int buf = 0;
    for (int ch = 0; ch < nch; ++ch) {
        if (ch + 1 < nch) {
            load_stage(buf ^ 1, (ch + 1) << 6);
            CP_COMMIT();
            CP_WAIT1();
        } else {
            CP_WAIT0();
        }
        __syncthreads();

        const uint32_t st = (uint32_t)buf * STAGE_BYTES;
        #pragma unroll
        for (int ks = 0; ks < 4; ++ks) {
            const uint32_t kb = ks * 32;
            uint32_t af[4][4];
            #pragma unroll
            for (int fm = 0; fm < 4; ++fm)
                ldm_x4(af[fm], aBase + st + fm * (16 * ROWB) + kb);
            uint32_t bf[2][4];
            #pragma unroll
            for (int p = 0; p < 2; ++p)
                ldm_x4(bf[p], bBase + st + p * (16 * ROWB) + kb);
            #pragma unroll
            for (int fm = 0; fm < 4; ++fm)
                #pragma unroll
                for (int fn = 0; fn < 4; ++fn)
                    mma_f16(acc[fm][fn], af[fm], bf[fn >> 1] + (fn & 1) * 2);
        }
        __syncthreads();
        buf ^= 1;
    }

    #pragma unroll
    for (int fm = 0; fm < 4; ++fm) {
        const int row0 = m0 + warp_m*64 + fm*16 + (lane >> 2);
        #pragma unroll
        for (int fn = 0; fn < 4; ++fn) {
            const int col = n0 + warp_n*32 + fn*8 + (lane & 3)*2;
            const float b0 = bias[col], b1 = bias[col + 1];
            float v0 = acc[fm][fn][0] + b0;
            float v1 = acc[fm][fn][1] + b1;
            float v2 = acc[fm][fn][2] + b0;
            float v3 = acc[fm][fn][3] + b1;
            if (EPI == 2) {
                const float2 r0 = *(const float2*)(res + (size_t)row0 * N + col);
                const float2 r1 = *(const float2*)(res + (size_t)(row0 + 8) * N + col);
                v0 += r0.x; v1 += r0.y; v2 += r1.x; v3 += r1.y;
                *(float2*)(outF + (size_t)row0 * N + col)       = make_float2(v0, v1);
                *(float2*)(outF + (size_t)(row0 + 8) * N + col) = make_float2(v2, v3);
            }
            if (EPI == 1) {
                v0 = gelu_tanh(v0); v1 = gelu_tanh(v1);
                v2 = gelu_tanh(v2); v3 = gelu_tanh(v3);
                *(uint32_t*)(outH + (size_t)row0 * N + col) =
                    packh2(__float2half_rn(v0), __float2half_rn(v1));
                *(uint32_t*)(outH + (size_t)(row0 + 8) * N + col) =
                    packh2(__float2half_rn(v2), __float2half_rn(v3));
            }
            if (EPI == 3) {
                const int which = col / CC;
                const int cc = col - which * CC;
                const int hh = cc >> 6, d = cc & 63;
                const int b0r = row0 >> 11, t0r = row0 & 2047;
                const int b1r = (row0 + 8) >> 11, t1r = (row0 + 8) & 2047;
                const size_t base0 = ((size_t)(b0r * HH + hh) * TT + t0r) * 64 + d;
                const size_t base1 = ((size_t)(b1r * HH + hh) * TT + t1r) * 64 + d;
                const float sc = (which == 0) ? QSCALE : 1.0f;
                __half* o = (which == 0) ? outH : (which == 1) ? oks : ovs;
                *(uint32_t*)(o + base0) = packh2(__float2half_rn(v0 * sc), __float2half_rn(v1 * sc));
                *(uint32_t*)(o + base1) = packh2(__float2half_rn(v2 * sc), __float2half_rn(v3 * sc));
            }
        }
    }
}

// ================= fp16 HMMA flash attention, f16x2 softmax + ones-MMA row sums ==========
// Q-tile 128 rows (8 warps x m16), K-tile 64, per-head layout [bh][T][64]. 2 CTAs/SM.
// smem: Q 16K | 3 KV stages of (K 8K | V 8K)
#define ATT_SMEM 65536
__global__ __launch_bounds__(256, 2) void attn_mma(
    const __half* __restrict__ qq,
    const __half* __restrict__ kk, const __half* __restrict__ vv,
    __half* __restrict__ yy)
{
    extern __shared__ __align__(1024) char smem[];
    const uint32_t sb = smem_u32(smem);
    enum { Q_O = 0, KV0 = 16384, KV_STRIDE = 16384, K_O = 0, V_O = 8192 };

    const int t = threadIdx.x, lane = t & 31, wid = t >> 5;
    const int qt = (int)(gridDim.x - 1) - (int)blockIdx.x;   // big tiles first
    const int bh = blockIdx.y;
    const int qbase = qt * 128;
    const size_t hb = (size_t)bh * TT * 64;
    const int warpQ = wid * 16;

    // Q copy
    #pragma unroll
    for (int i = 0; i < 4; ++i) {
        const int idx = t + i * 256;
        const int row = idx >> 3, seg = idx & 7;
        const uint32_t so = SMEM_SWIZZLE_128B((uint32_t)(row * 128 + seg * 16));
        cp16(sb + Q_O + so, qq + hb + (size_t)(qbase + row) * 64 + seg * 8);
    }
    auto load_kv = [&](int buf, int kt) {
        const uint32_t dst = sb + KV0 + buf * KV_STRIDE;
        #pragma unroll
        for (int i = 0; i < 2; ++i) {
            const int idx = t + i * 256;
            const int row = idx >> 3, seg = idx & 7;
            const uint32_t so = SMEM_SWIZZLE_128B((uint32_t)(row * 128 + seg * 16));
            const size_t g = hb + (size_t)(kt * 64 + row) * 64 + seg * 8;
            cp16(dst + K_O + so, kk + g);
            cp16(dst + V_O + so, vv + g);
        }
    };
    const int nkt = 2 * qt + 2;
    load_kv(0, 0);
    CP_COMMIT();
    load_kv(1, 1);
    CP_COMMIT();

    uint32_t qa[4][4];
    float o[8][4];
    #pragma unroll
    for (int j = 0; j < 8; ++j)
        #pragma unroll
        for (int e = 0; e < 4; ++e) o[j][e] = 0.f;
    float m0r = -1e30f, m1r = -1e30f, l0r = 0.f, l1r = 0.f;

    const uint32_t ones2b[2] = {0x3C003C00u, 0x3C003C00u};   // fp16 {1,1} B fragment

    int buf = 0;
    for (int kt = 0; kt < nkt; ++kt) {
        if (kt == nkt - 1) { CP_WAIT0(); } else { CP_WAIT1(); }
        __syncthreads();
        if (kt + 2 < nkt) {
            int nb = buf + 2; if (nb >= 3) nb -= 3;
            load_kv(nb, kt + 2);
            CP_COMMIT();
        }

        if (kt == 0) {
            const uint32_t qrow = (uint32_t)(warpQ + (lane & 15));
            const uint32_t qbyt = (uint32_t)((lane >> 4) * 16);
            #pragma unroll
            for (int s = 0; s < 4; ++s)
                ldm_x4(qa[s], sb + Q_O + SMEM_SWIZZLE_128B(qrow * 128 + s * 32 + qbyt));
        }
        const uint32_t st = sb + KV0 + buf * KV_STRIDE;

        // ---- S = Q16 K16^T ----
        float sacc[8][4];
        #pragma unroll
        for (int j = 0; j < 8; ++j) { sacc[j][0]=0.f; sacc[j][1]=0.f; sacc[j][2]=0.f; sacc[j][3]=0.f; }
        #pragma unroll
        for (int j = 0; j < 8; ++j) {
            const uint32_t krow = (uint32_t)(j * 8 + (lane & 7));
            const uint32_t kbyt = (uint32_t)(((lane >> 3) & 3) * 16);
            uint32_t kb0[4], kb1[4];
            ldm_x4(kb0, st + K_O + SMEM_SWIZZLE_128B(krow * 128 + kbyt));
            ldm_x4(kb1, st + K_O + SMEM_SWIZZLE_128B(krow * 128 + 64 + kbyt));
            mma_f16(sacc[j], qa[0], kb0 + 0); mma_f16(sacc[j], qa[1], kb0 + 2);
            mma_f16(sacc[j], qa[2], kb1 + 0); mma_f16(sacc[j], qa[3], kb1 + 2);
        }

        // ---- causal mask (last two K-tiles only) ----
        if (kt >= 2 * qt) {
            const int r0 = qbase + warpQ + (lane >> 2);
            #pragma unroll
            for (int j = 0; j < 8; ++j) {
                const int c = kt * 64 + j * 8 + (lane & 3) * 2;
                if (c     > r0)     sacc[j][0] = -1e30f;
                if (c + 1 > r0)     sacc[j][1] = -1e30f;
                if (c     > r0 + 8) sacc[j][2] = -1e30f;
                if (c + 1 > r0 + 8) sacc[j][3] = -1e30f;
            }
        }

        // ---- online softmax (base-2): max in fp32, exp in f16x2, row sums via ones-MMA ----
        float tm0 = -1e30f, tm1 = -1e30f;
        #pragma unroll
        for (int j = 0; j < 8; ++j) {
            tm0 = fmaxf(tm0, fmaxf(sacc[j][0], sacc[j][1]));
            tm1 = fmaxf(tm1, fmaxf(sacc[j][2], sacc[j][3]));
        }
        tm0 = fmaxf(tm0, __shfl_xor_sync(0xffffffffu, tm0, 1));
        tm0 = fmaxf(tm0, __shfl_xor_sync(0xffffffffu, tm0, 2));
        tm1 = fmaxf(tm1, __shfl_xor_sync(0xffffffffu, tm1, 1));
        tm1 = fmaxf(tm1, __shfl_xor_sync(0xffffffffu, tm1, 2));
        const float mn0 = fmaxf(m0r, tm0), mn1 = fmaxf(m1r, tm1);
        const float al0 = ex2f(m0r - mn0), al1 = ex2f(m1r - mn1);
        m0r = mn0; m1r = mn1;

        uint32_t pa[4][4];
        float rsacc[4] = {0.f, 0.f, 0.f, 0.f};
        #pragma unroll
        for (int s = 0; s < 4; ++s) {
            pa[s][0] = h2ex2(f2h2(sacc[2*s][0]   - mn0, sacc[2*s][1]   - mn0));
            pa[s][1] = h2ex2(f2h2(sacc[2*s][2]   - mn1, sacc[2*s][3]   - mn1));
            pa[s][2] = h2ex2(f2h2(sacc[2*s+1][0] - mn0, sacc[2*s+1][1] - mn0));
            pa[s][3] = h2ex2(f2h2(sacc[2*s+1][2] - mn1, sacc[2*s+1][3] - mn1));
            mma_f16(rsacc, pa[s], ones2b);   // row sums: every n col identical
        }
        l0r = l0r * al0 + rsacc[0];
        l1r = l1r * al1 + rsacc[2];
        #pragma unroll
        for (int j = 0; j < 8; ++j) {
            o[j][0] *= al0; o[j][1] *= al0; o[j][2] *= al1; o[j][3] *= al1;
        }

        // ---- O += P16 V16 (V^T via ldmatrix.trans) ----
        #pragma unroll
        for (int jp = 0; jp < 4; ++jp) {
            #pragma unroll
            for (int s = 0; s < 4; ++s) {
                const uint32_t vrow = (uint32_t)(s * 16 + (lane & 15));
                const uint32_t vbyt = (uint32_t)(jp * 32 + (lane >> 4) * 16);
                uint32_t vb[4];
                ldm_x4_trans(vb, st + V_O + SMEM_SWIZZLE_128B(vrow * 128 + vbyt));
                mma_f16(o[2*jp],     pa[s], vb + 0);
                mma_f16(o[2*jp + 1], pa[s], vb + 2);
            }
        }
        ++buf; if (buf >= 3) buf -= 3;
    }

    // ---- epilogue: normalize, write y (single fp16) ----
    const float inv0 = 1.0f / l0r, inv1 = 1.0f / l1r;
    const int b = bh / HH, h = bh - b * HH;
    const size_t row0 = (size_t)b * TT + qbase + warpQ + (lane >> 2);
    #pragma unroll
    for (int j = 0; j < 8; ++j) {
        const int col = h * 64 + j * 8 + (lane & 3) * 2;
        *(uint32_t*)(yy + row0 * CC + col) =
            packh2(__float2half_rn(o[j][0] * inv0), __float2half_rn(o[j][1] * inv0));
        *(uint32_t*)(yy + (row0 + 8) * CC + col) =
            packh2(__float2half_rn(o[j][2] * inv1), __float2half_rn(o[j][3] * inv1));
    }
}

// ================= launch =================
extern "C" void kernel_launch(void* const* d_in, const int* in_sizes, int n_in,
                              void* d_out, int out_size)
{
    const float* x       = (const float*)d_in[0];
    const float* ln1_g   = (const float*)d_in[1];
    const float* ln1_b   = (const float*)d_in[2];
    const float* w_attn  = (const float*)d_in[3];
    const float* b_attn  = (const float*)d_in[4];
    const float* w_aproj = (const float*)d_in[5];
    const float* b_aproj = (const float*)d_in[6];
    const float* ln2_g   = (const float*)d_in[7];
    const float* ln2_b   = (const float*)d_in[8];
    const float* w_fc    = (const float*)d_in[9];
    const float* b_fc    = (const float*)d_in[10];
    const float* w_mproj = (const float*)d_in[11];
    const float* b_mproj = (const float*)d_in[12];
    float* out = (float*)d_out;

    __half *h1,*y,*h2,*fc,*wq,*wa,*wf,*wm,*qs,*ks,*vs;
    float *x1;
    cudaGetSymbolAddress((void**)&h1, g_h1);
    cudaGetSymbolAddress((void**)&y,  g_y);
    cudaGetSymbolAddress((void**)&x1, g_x1);
    cudaGetSymbolAddress((void**)&h2, g_h2);
    cudaGetSymbolAddress((void**)&fc, g_fc);
    cudaGetSymbolAddress((void**)&wq, g_wq);
    cudaGetSymbolAddress((void**)&wa, g_wa);
    cudaGetSymbolAddress((void**)&wf, g_wf);
    cudaGetSymbolAddress((void**)&wm, g_wm);
    cudaGetSymbolAddress((void**)&qs, g_qs);
    cudaGetSymbolAddress((void**)&ks, g_ks);
    cudaGetSymbolAddress((void**)&vs, g_vs);

    cudaFuncSetAttribute(hmma_gemm<1>, cudaFuncAttributeMaxDynamicSharedMemorySize, GEMM_SMEM);
    cudaFuncSetAttribute(hmma_gemm<2>, cudaFuncAttributeMaxDynamicSharedMemorySize, GEMM_SMEM);
    cudaFuncSetAttribute(hmma_gemm<3>, cudaFuncAttributeMaxDynamicSharedMemorySize, GEMM_SMEM);
    cudaFuncSetAttribute(attn_mma,     cudaFuncAttributeMaxDynamicSharedMemorySize, ATT_SMEM);

    // 0) fused prep: weight transposes + LN1
    prep_kernel<<<7936, 256>>>(w_attn, w_aproj, w_fc, w_mproj,
                               wq, wa, wf, wm, x, ln1_g, ln1_b, h1);
    // 1) q/k/v = per-head(h1 @ w_attn + b_attn), Q scaled
    hmma_gemm<3><<<dim3(QKVC/128, NROWS/128), 256, GEMM_SMEM>>>(
        h1, wq, b_attn, nullptr, nullptr, qs, ks, vs, NROWS, QKVC, CC);
    // 2) y = attention
    attn_mma<<<dim3(TT/128, BB*HH), 256, ATT_SMEM>>>(qs, ks, vs, y);
    // 3) x1 = y @ w_aproj + b_aproj + x
    hmma_gemm<2><<<dim3(CC/128, NROWS/128), 256, GEMM_SMEM>>>(
        y, wa, b_aproj, x, x1, nullptr, nullptr, nullptr, NROWS, CC, CC);
    // 4) h2 = ln2(x1)
    ln_h_kernel<<<NROWS/8, 256>>>(x1, ln2_g, ln2_b, h2);
    // 5) fc = gelu(h2 @ w_fc + b_fc)
    hmma_gemm<1><<<dim3(FFC/128, NROWS/128), 256, GEMM_SMEM>>>(
        h2, wf, b_fc, nullptr, nullptr, fc, nullptr, nullptr, NROWS, FFC, CC);
    // 6) out = fc @ w_mproj + b_mproj + x1
    hmma_gemm<2><<<dim3(CC/128, NROWS/128), 256, GEMM_SMEM>>>(
        fc, wm, b_mproj, x1, out, nullptr, nullptr, nullptr, NROWS, CC, FFC);
}